// round 13
// baseline (speedup 1.0000x reference)
#include <cuda_runtime.h>
#include <stdint.h>

#define BB 512
#define TT 2048
#define DD 10
#define HH 20
#define NCTA 8
#define BPC (BB / NCTA)                  // 64 batches per CTA
#define SCAN_THREADS (BPC * (HH / 2))    // 640 threads (each owns 2 h-lanes of one batch)

// ---------------- device scratch (no allocations allowed) ----------------
__device__ float    g_xWT[(size_t)TT * BB * HH];   // xW in [T,B,H] layout (84 MB)
__device__ unsigned g_absmax_x_bits;
__device__ float    g_consts[8];                   // [0]=s_wi [1]=inv_wi [2]=s_b [3]=inv_b [4]=s_wh [5]=s_h0 [6]=inv_h0
__device__ int      g_WhQ[HH][5];                  // Wh quantized, packed int8x4 along k

// ---------------- helpers ----------------
__device__ __forceinline__ uint32_t smem_u32(const void* p) {
    return (uint32_t)__cvta_generic_to_shared(p);
}

// power-of-two per-tensor scale: scale = 2^ceil(log2(max(m,1e-10)))/128, inv exact
__device__ __forceinline__ float pot_scale(float maxabs, float* inv) {
    float m = fmaxf(maxabs, 1e-10f);
    float e = ceilf(log2f(m));
    *inv = exp2f(7.0f - e);
    return exp2f(e - 7.0f);
}

// order-preserving float<->uint encoding (for REDUX.MAX/MIN on floats)
__device__ __forceinline__ unsigned fenc(float f) {
    int i = __float_as_int(f);
    return (unsigned)(i ^ ((i >> 31) | 0x80000000));
}
__device__ __forceinline__ float fdec(unsigned u) {
    int i = (u & 0x80000000u) ? (int)(u & 0x7FFFFFFFu) : ~(int)u;
    return __int_as_float(i);
}

__device__ __forceinline__ float qclip(float v) {
    return fminf(fmaxf(v, -128.0f), 127.0f);
}

// block-wide maxabs over n floats (256 threads), returns to ALL threads
__device__ float block_maxabs(const float* p, int n, unsigned* sh) {
    unsigned loc = 0u;
    for (int i = threadIdx.x; i < n; i += blockDim.x)
        loc = max(loc, __float_as_uint(fabsf(p[i])));
    loc = __reduce_max_sync(0xFFFFFFFFu, loc);
    int w = threadIdx.x >> 5, l = threadIdx.x & 31;
    if (l == 0) sh[w] = loc;
    __syncthreads();
    if (threadIdx.x == 0) {
        unsigned m = 0u;
        for (int i = 0; i < (int)(blockDim.x >> 5); i++) m = max(m, sh[i]);
        sh[15] = m;
    }
    __syncthreads();
    return __uint_as_float(sh[15]);
}

// cluster-scope acquire wait on local mbarrier parity
__device__ __forceinline__ void mbar_wait_cluster(uint32_t addr, unsigned parity) {
    unsigned done;
    asm volatile(
        "{\n\t.reg .pred P;\n\t"
        "mbarrier.try_wait.parity.acquire.cluster.shared::cta.b64 P, [%1], %2;\n\t"
        "selp.b32 %0, 1, 0, P;\n\t}"
        : "=r"(done) : "r"(addr), "r"(parity) : "memory");
    if (!done) {
        asm volatile(
            "{\n\t.reg .pred P;\n\t"
            "WLOOP_%=:\n\t"
            "mbarrier.try_wait.parity.acquire.cluster.shared::cta.b64 P, [%0], %1, 0x989680;\n\t"
            "@P bra.uni WDONE_%=;\n\t"
            "bra.uni WLOOP_%=;\n\t"
            "WDONE_%=:\n\t}"
            :: "r"(addr), "r"(parity) : "memory");
    }
}

// ---------------- kernel 1: scales for W_ih / W_hh / b / h0, quantize Wh, reset x-max ----------------
__global__ void k_prep(const float* __restrict__ Wi, const float* __restrict__ Wh,
                       const float* __restrict__ bias, const float* __restrict__ h0) {
    __shared__ unsigned sh[16];
    __shared__ float s_inv_wh;
    float m_wi = block_maxabs(Wi,   HH * DD, sh);
    float m_wh = block_maxabs(Wh,   HH * HH, sh);
    float m_b  = block_maxabs(bias, HH,      sh);
    float m_h0 = block_maxabs(h0,   BB * HH, sh);
    if (threadIdx.x == 0) {
        float inv, s;
        s = pot_scale(m_wi, &inv); g_consts[0] = s; g_consts[1] = inv;
        s = pot_scale(m_b,  &inv); g_consts[2] = s; g_consts[3] = inv;
        s = pot_scale(m_wh, &inv); g_consts[4] = s; s_inv_wh = inv;
        s = pot_scale(m_h0, &inv); g_consts[5] = s; g_consts[6] = inv;
        g_absmax_x_bits = 0u;
    }
    __syncthreads();
    float inv_wh = s_inv_wh;
    if (threadIdx.x < HH * 5) {
        int h = threadIdx.x / 5, kk = threadIdx.x % 5;
        int packv = 0;
        #pragma unroll
        for (int j = 0; j < 4; j++) {
            float q = qclip(rintf(Wh[h * HH + kk * 4 + j] * inv_wh));
            packv |= (((int)q) & 0xFF) << (8 * j);
        }
        g_WhQ[h][kk] = packv;
    }
}

// ---------------- kernel 2: global maxabs(x) ----------------
__global__ void k_absmax_x(const float* __restrict__ x, int n4) {
    const float4* xp = (const float4*)x;
    unsigned loc = 0u;
    for (int i = blockIdx.x * blockDim.x + threadIdx.x; i < n4; i += gridDim.x * blockDim.x) {
        float4 v = xp[i];
        loc = max(loc, __float_as_uint(fabsf(v.x)));
        loc = max(loc, __float_as_uint(fabsf(v.y)));
        loc = max(loc, __float_as_uint(fabsf(v.z)));
        loc = max(loc, __float_as_uint(fabsf(v.w)));
    }
    loc = __reduce_max_sync(0xFFFFFFFFu, loc);
    __shared__ unsigned sh[8];
    int w = threadIdx.x >> 5, l = threadIdx.x & 31;
    if (l == 0) sh[w] = loc;
    __syncthreads();
    if (threadIdx.x == 0) {
        unsigned m = 0u;
        #pragma unroll
        for (int i = 0; i < 8; i++) m = max(m, sh[i]);
        atomicMax(&g_absmax_x_bits, m);
    }
}

// ---------------- kernel 3: xWT[t][b][h] = quant(x) . Wiq[h] + bq[h] ----------------
__global__ void k_xw(const float* __restrict__ x, const float* __restrict__ Wi,
                     const float* __restrict__ bias) {
    __shared__ float Wiq[HH][DD];
    __shared__ float bq[HH];
    int tid = threadIdx.x;
    if (tid < HH * DD)
        Wiq[tid / DD][tid % DD] = qclip(rintf(Wi[tid] * g_consts[1])) * g_consts[0];
    else if (tid < HH * DD + HH) {
        int h = tid - HH * DD;
        bq[h] = qclip(rintf(bias[h] * g_consts[3])) * g_consts[2];
    }
    float inv_sx;
    float sx = pot_scale(__uint_as_float(g_absmax_x_bits), &inv_sx);
    __syncthreads();

    int g = blockIdx.x * blockDim.x + tid;   // g = t*512 + b (b fastest -> coalesced writes)
    int t = g >> 9;
    int b = g & 511;
    const float2* xp = (const float2*)(x + ((size_t)b * TT + t) * DD);
    float xq[DD];
    #pragma unroll
    for (int k = 0; k < 5; k++) {
        float2 v = xp[k];
        xq[2 * k]     = qclip(rintf(v.x * inv_sx)) * sx;
        xq[2 * k + 1] = qclip(rintf(v.y * inv_sx)) * sx;
    }
    float acc[HH];
    #pragma unroll
    for (int h = 0; h < HH; h++) {
        float a = bq[h];
        #pragma unroll
        for (int d = 0; d < DD; d++) a = fmaf(xq[d], Wiq[h][d], a);
        acc[h] = a;
    }
    float2* op = (float2*)(g_xWT + ((size_t)t * BB + b) * HH);
    #pragma unroll
    for (int k = 0; k < 10; k++) op[k] = make_float2(acc[2 * k], acc[2 * k + 1]);
}

// ---------------- kernel 4: the serialized quantized RNN scan (8-CTA cluster) ----------------
__global__ void __cluster_dims__(NCTA, 1, 1) __launch_bounds__(SCAN_THREADS, 1)
k_scan(const float* __restrict__ h0, float* __restrict__ out) {
    __shared__ int hq[BPC][8];                         // packed int8 h-state, 5 ints used/row
    __shared__ unsigned partials[20][2];               // per-warp (max,min) encoded
    __shared__ unsigned long long slots[2][NCTA];      // double-buffered cross-CTA partials
    __shared__ unsigned long long mbar;

    int tid  = threadIdx.x;
    int lane = tid & 31, warp = tid >> 5;
    int b_loc = tid / 10;
    int h0i   = (tid % 10) * 2;
    unsigned rank;
    asm("mov.u32 %0, %%cluster_ctarank;" : "=r"(rank));
    int b_glob = (int)rank * BPC + b_loc;

    uint32_t mbar_addr = smem_u32(&mbar);
    uint32_t slot_base = smem_u32(&slots[0][0]);

    if (tid == 0) {
        asm volatile("mbarrier.init.shared.b64 [%0], %1;" :: "r"(mbar_addr), "r"(NCTA) : "memory");
    }

    // Wh rows for my two h-lanes, register-resident for all 2048 steps
    int w0[5], w1[5];
    #pragma unroll
    for (int k = 0; k < 5; k++) { w0[k] = g_WhQ[h0i][k]; w1[k] = g_WhQ[h0i + 1][k]; }
    float swh    = g_consts[4];
    float s2prev = g_consts[5];
    float inv_h0 = g_consts[6];

    // init h-state from quantized h0
    {
        float a = h0[(size_t)b_glob * HH + h0i];
        float c = h0[(size_t)b_glob * HH + h0i + 1];
        int q0 = (int)qclip(rintf(a * inv_h0));
        int q1 = (int)qclip(rintf(c * inv_h0));
        unsigned short pk = (unsigned short)((q0 & 0xFF) | ((q1 & 0xFF) << 8));
        *((unsigned short*)((char*)&hq[b_loc][0] + h0i)) = pk;
    }
    __syncthreads();
    asm volatile("barrier.cluster.arrive.aligned;" ::: "memory");
    asm volatile("barrier.cluster.wait.aligned;"   ::: "memory");

    float2 xw = *(const float2*)(g_xWT + ((size_t)0 * BB + b_glob) * HH + h0i);
    float* outp = out + (size_t)b_glob * TT * HH + h0i;

    for (int t = 0; t < TT; ++t) {
        // prefetch next timestep's xW
        float2 xw_n = make_float2(0.f, 0.f);
        if (t + 1 < TT)
            xw_n = *(const float2*)(g_xWT + ((size_t)(t + 1) * BB + b_glob) * HH + h0i);

        // recurrent contribution: exact int8 dot x (s2*swh)
        int id0 = 0, id1 = 0;
        #pragma unroll
        for (int k = 0; k < 5; k++) {
            int hv = hq[b_loc][k];
            id0 = __dp4a(hv, w0[k], id0);
            id1 = __dp4a(hv, w1[k], id1);
        }
        float rs = s2prev * swh;
        float a0 = fmaf((float)id0, rs, xw.x);
        float a1 = fmaf((float)id1, rs, xw.y);

        // warp-level max/min via REDUX on order-preserving uints
        unsigned e0 = fenc(a0), e1 = fenc(a1);
        unsigned em = __reduce_max_sync(0xFFFFFFFFu, max(e0, e1));
        unsigned en = __reduce_min_sync(0xFFFFFFFFu, min(e0, e1));
        if (lane == 0) { partials[warp][0] = em; partials[warp][1] = en; }
        __syncthreads();

        if (warp == 0) {
            unsigned pm = (lane < 20) ? partials[lane][0] : 0u;
            unsigned pn = (lane < 20) ? partials[lane][1] : 0xFFFFFFFFu;
            pm = __reduce_max_sync(0xFFFFFFFFu, pm);
            pn = __reduce_min_sync(0xFFFFFFFFu, pn);
            if (lane == 0) {
                unsigned long long pk = (((unsigned long long)pm) << 32) | (unsigned long long)pn;
                uint32_t myslot = slot_base + (uint32_t)(((t & 1) * NCTA + (int)rank) * 8);
                #pragma unroll
                for (int c = 0; c < NCTA; c++) {
                    uint32_t r;
                    asm("mapa.shared::cluster.u32 %0, %1, %2;" : "=r"(r) : "r"(myslot), "r"(c));
                    asm volatile("st.shared::cluster.u64 [%0], %1;" :: "r"(r), "l"(pk) : "memory");
                }
                #pragma unroll
                for (int c = 0; c < NCTA; c++) {
                    uint32_t r;
                    asm("mapa.shared::cluster.u32 %0, %1, %2;" : "=r"(r) : "r"(mbar_addr), "r"(c));
                    asm volatile("mbarrier.arrive.release.cluster.shared::cluster.b64 _, [%0];"
                                 :: "r"(r) : "memory");
                }
            }
        }

        // wait for all 8 CTAs' partials
        mbar_wait_cluster(mbar_addr, (unsigned)(t & 1));

        // global (mx, mn)
        unsigned gm = 0u, gn = 0xFFFFFFFFu;
        #pragma unroll
        for (int c = 0; c < NCTA; c++) {
            unsigned long long v = slots[t & 1][c];
            gm = max(gm, (unsigned)(v >> 32));
            gn = min(gn, (unsigned)(v & 0xFFFFFFFFull));
        }
        float mx = fdec(gm), mn = fdec(gn);

        // gate-acc quant scale from global maxabs
        float inv1;
        float s1 = pot_scale(fmaxf(mx, -mn), &inv1);
        // output quant scale derived analytically: maxabs(tanh(q(acc))) = tanh(max(q(mx), -q(mn)))
        float qmx = qclip(rintf(mx * inv1)) * s1;
        float qmn = qclip(rintf(mn * inv1)) * s1;
        float habs = tanhf(fmaxf(qmx, -qmn));
        float inv2;
        float s2 = pot_scale(habs, &inv2);

        // elementwise: quant -> tanh -> quant
        float q0 = qclip(rintf(a0 * inv1));
        float q1 = qclip(rintf(a1 * inv1));
        float t0 = tanhf(q0 * s1);
        float t1 = tanhf(q1 * s1);
        float n0 = qclip(rintf(t0 * inv2));
        float n1 = qclip(rintf(t1 * inv2));

        // emit output, update int8 h-state
        *(float2*)(outp + (size_t)t * HH) = make_float2(n0 * s2, n1 * s2);
        unsigned short pk16 = (unsigned short)((((int)n0) & 0xFF) | ((((int)n1) & 0xFF) << 8));
        *((unsigned short*)((char*)&hq[b_loc][0] + h0i)) = pk16;

        s2prev = s2;
        xw = xw_n;
        __syncthreads();
    }
}

// ---------------- launch ----------------
extern "C" void kernel_launch(void* const* d_in, const int* in_sizes, int n_in,
                              void* d_out, int out_size) {
    const float* x    = (const float*)d_in[0];
    const float* h0   = (const float*)d_in[1];
    const float* Wi   = (const float*)d_in[2];
    const float* Wh   = (const float*)d_in[3];
    const float* bias = (const float*)d_in[4];
    float* out = (float*)d_out;

    k_prep<<<1, 256>>>(Wi, Wh, bias, h0);
    k_absmax_x<<<1024, 256>>>(x, (BB * TT * DD) / 4);
    k_xw<<<(BB * TT) / 256, 256>>>(x, Wi, bias);
    k_scan<<<NCTA, SCAN_THREADS>>>(h0, out);
}

// round 14
// speedup vs baseline: 2.2104x; 2.2104x over previous
#include <cuda_runtime.h>
#include <stdint.h>

#define BB 512
#define TT 2048
#define DD 10
#define HH 20
#define NCTA 8
#define BPC (BB / NCTA)                 // 64 batches per CTA
#define NWARP 22                        // 3 batches per warp (batch never straddles a warp)
#define SCAN_THREADS (NWARP * 32)       // 704

// ---------------- device scratch (no allocations allowed) ----------------
__device__ float    g_xWT[(size_t)TT * BB * HH];    // xW in [T,B,H] layout (84 MB)
__device__ unsigned g_absmax_x_bits;
__device__ float    g_consts[8];                    // [0]=s_wi [1]=inv_wi [2]=s_b [3]=inv_b [4]=s_wh [5]=s_h0 [6]=inv_h0
__device__ int      g_WhQ[HH][5];                   // Wh quantized, packed int8x4 along k
__device__ unsigned long long g_slots[TT * NCTA];   // per-step per-CTA (max,min), sentinel hi==0

// ---------------- helpers ----------------
// power-of-two per-tensor scale via exponent bits: scale = 2^ceil(log2(max(m,1e-10)))/128
// (m >= 1e-10 is always normal, so exponent-field + mantissa-bump is exactly ceil(log2))
__device__ __forceinline__ float pot_scale(float maxabs, float* inv) {
    float m = fmaxf(maxabs, 1e-10f);
    int bits = __float_as_int(m);
    int e = ((bits >> 23) & 255) - 127 + (((bits & 0x7FFFFF) != 0) ? 1 : 0);
    *inv = __int_as_float((134 - e) << 23);   // 2^(7-e)
    return __int_as_float((e + 120) << 23);   // 2^(e-7)
}

// order-preserving float<->uint encoding (REDUX.MAX/MIN on floats).
// Encoded value of any real float is >= 0x007FFFFF, so high-word 0 is a safe sentinel.
__device__ __forceinline__ unsigned fenc(float f) {
    int i = __float_as_int(f);
    return (unsigned)(i ^ ((i >> 31) | 0x80000000));
}
__device__ __forceinline__ float fdec(unsigned u) {
    int i = (u & 0x80000000u) ? (int)(u & 0x7FFFFFFFu) : ~(int)u;
    return __int_as_float(i);
}

__device__ __forceinline__ float qclip(float v) {
    return fminf(fmaxf(v, -128.0f), 127.0f);
}

// block-wide maxabs over n floats (256 threads), result to ALL threads
__device__ float block_maxabs(const float* p, int n, unsigned* sh) {
    unsigned loc = 0u;
    for (int i = threadIdx.x; i < n; i += blockDim.x)
        loc = max(loc, __float_as_uint(fabsf(p[i])));
    loc = __reduce_max_sync(0xFFFFFFFFu, loc);
    int w = threadIdx.x >> 5, l = threadIdx.x & 31;
    if (l == 0) sh[w] = loc;
    __syncthreads();
    if (threadIdx.x == 0) {
        unsigned m = 0u;
        for (int i = 0; i < (int)(blockDim.x >> 5); i++) m = max(m, sh[i]);
        sh[15] = m;
    }
    __syncthreads();
    return __uint_as_float(sh[15]);
}

// ---------------- kernel 1: scales for W_ih / W_hh / b / h0, quantize Wh, reset x-max ----------------
__global__ void k_prep(const float* __restrict__ Wi, const float* __restrict__ Wh,
                       const float* __restrict__ bias, const float* __restrict__ h0) {
    __shared__ unsigned sh[16];
    __shared__ float s_inv_wh;
    float m_wi = block_maxabs(Wi,   HH * DD, sh);
    float m_wh = block_maxabs(Wh,   HH * HH, sh);
    float m_b  = block_maxabs(bias, HH,      sh);
    float m_h0 = block_maxabs(h0,   BB * HH, sh);
    if (threadIdx.x == 0) {
        float inv, s;
        s = pot_scale(m_wi, &inv); g_consts[0] = s; g_consts[1] = inv;
        s = pot_scale(m_b,  &inv); g_consts[2] = s; g_consts[3] = inv;
        s = pot_scale(m_wh, &inv); g_consts[4] = s; s_inv_wh = inv;
        s = pot_scale(m_h0, &inv); g_consts[5] = s; g_consts[6] = inv;
        g_absmax_x_bits = 0u;
    }
    __syncthreads();
    float inv_wh = s_inv_wh;
    if (threadIdx.x < HH * 5) {
        int h = threadIdx.x / 5, kk = threadIdx.x % 5;
        int packv = 0;
        #pragma unroll
        for (int j = 0; j < 4; j++) {
            float q = qclip(rintf(Wh[h * HH + kk * 4 + j] * inv_wh));
            packv |= (((int)q) & 0xFF) << (8 * j);
        }
        g_WhQ[h][kk] = packv;
    }
}

// ---------------- kernel 2: global maxabs(x) + sentinel-init the exchange slots ----------------
__global__ void k_absmax_x(const float* __restrict__ x, int n4) {
    const float4* xp = (const float4*)x;
    unsigned loc = 0u;
    int stride = gridDim.x * blockDim.x;
    int gid = blockIdx.x * blockDim.x + threadIdx.x;
    for (int i = gid; i < n4; i += stride) {
        float4 v = xp[i];
        loc = max(loc, __float_as_uint(fabsf(v.x)));
        loc = max(loc, __float_as_uint(fabsf(v.y)));
        loc = max(loc, __float_as_uint(fabsf(v.z)));
        loc = max(loc, __float_as_uint(fabsf(v.w)));
    }
    // re-init exchange slots every launch (graph replays the whole sequence)
    for (int i = gid; i < TT * NCTA; i += stride) g_slots[i] = 0ull;

    loc = __reduce_max_sync(0xFFFFFFFFu, loc);
    __shared__ unsigned sh[8];
    int w = threadIdx.x >> 5, l = threadIdx.x & 31;
    if (l == 0) sh[w] = loc;
    __syncthreads();
    if (threadIdx.x == 0) {
        unsigned m = 0u;
        #pragma unroll
        for (int i = 0; i < 8; i++) m = max(m, sh[i]);
        atomicMax(&g_absmax_x_bits, m);
    }
}

// ---------------- kernel 3: xWT[t][b][h] = quant(x) . Wiq[h] + bq[h] ----------------
__global__ void k_xw(const float* __restrict__ x, const float* __restrict__ Wi,
                     const float* __restrict__ bias) {
    __shared__ float Wiq[HH][DD];
    __shared__ float bq[HH];
    int tid = threadIdx.x;
    if (tid < HH * DD)
        Wiq[tid / DD][tid % DD] = qclip(rintf(Wi[tid] * g_consts[1])) * g_consts[0];
    else if (tid < HH * DD + HH) {
        int h = tid - HH * DD;
        bq[h] = qclip(rintf(bias[h] * g_consts[3])) * g_consts[2];
    }
    float inv_sx;
    float sx = pot_scale(__uint_as_float(g_absmax_x_bits), &inv_sx);
    __syncthreads();

    int g = blockIdx.x * blockDim.x + tid;   // g = t*512 + b (b fastest -> coalesced writes)
    int t = g >> 9;
    int b = g & 511;
    const float2* xp = (const float2*)(x + ((size_t)b * TT + t) * DD);
    float xq[DD];
    #pragma unroll
    for (int k = 0; k < 5; k++) {
        float2 v = xp[k];
        xq[2 * k]     = qclip(rintf(v.x * inv_sx)) * sx;
        xq[2 * k + 1] = qclip(rintf(v.y * inv_sx)) * sx;
    }
    float acc[HH];
    #pragma unroll
    for (int h = 0; h < HH; h++) {
        float a = bq[h];
        #pragma unroll
        for (int d = 0; d < DD; d++) a = fmaf(xq[d], Wiq[h][d], a);
        acc[h] = a;
    }
    float2* op = (float2*)(g_xWT + ((size_t)t * BB + b) * HH);
    #pragma unroll
    for (int k = 0; k < 10; k++) op[k] = make_float2(acc[2 * k], acc[2 * k + 1]);
}

// ---------------- kernel 4: serialized quantized RNN scan (8 independent CTAs, L2 exchange) ----------------
__global__ void __launch_bounds__(SCAN_THREADS, 1)
k_scan(const float* __restrict__ h0, float* __restrict__ out) {
    __shared__ int hq[BPC][8];                 // packed int8 h-state (5 ints used per row)
    __shared__ unsigned partials[NWARP][2];    // per-warp (max,min) encoded
    __shared__ unsigned long long sh_comb;     // CTA-wide broadcast of global (max,min)

    int tid  = threadIdx.x;
    int lane = tid & 31, warp = tid >> 5;
    int sub   = lane / 10;                     // 0..2 real, >=3 idle
    int b_loc = warp * 3 + sub;
    bool active = (lane < 30) && (b_loc < BPC);
    int  b_safe = active ? b_loc : 0;
    int  h0i    = (lane % 10) * 2;
    int  rank   = blockIdx.x;
    int  b_glob = rank * BPC + b_safe;

    // Wh rows for my two h-lanes, register-resident across all 2048 steps
    int w0[5], w1[5];
    #pragma unroll
    for (int k = 0; k < 5; k++) { w0[k] = g_WhQ[h0i][k]; w1[k] = g_WhQ[h0i + 1][k]; }
    float swh    = g_consts[4];
    float s2prev = g_consts[5];
    float inv_h0 = g_consts[6];

    // init int8 h-state from quantized h0
    if (active) {
        float a = h0[(size_t)b_glob * HH + h0i];
        float c = h0[(size_t)b_glob * HH + h0i + 1];
        int q0 = (int)qclip(rintf(a * inv_h0));
        int q1 = (int)qclip(rintf(c * inv_h0));
        unsigned short pk = (unsigned short)((q0 & 0xFF) | ((q1 & 0xFF) << 8));
        *((unsigned short*)((char*)&hq[b_safe][0] + h0i)) = pk;
    }
    __syncthreads();

    float2 xw = make_float2(0.f, 0.f);
    if (active) xw = *(const float2*)(g_xWT + ((size_t)0 * BB + b_glob) * HH + h0i);
    float* outp = out + (size_t)b_glob * TT * HH + h0i;

    unsigned long long slots_g = (unsigned long long)__cvta_generic_to_global(&g_slots[0]);

    for (int t = 0; t < TT; ++t) {
        // prefetch next timestep's xW (hidden under this step's sync chain)
        float2 xw_n = make_float2(0.f, 0.f);
        if (active && (t + 1 < TT))
            xw_n = *(const float2*)(g_xWT + ((size_t)(t + 1) * BB + b_glob) * HH + h0i);

        // recurrent contribution: exact int8 dot times (s2*swh)
        int id0 = 0, id1 = 0;
        #pragma unroll
        for (int k = 0; k < 5; k++) {
            int hv = hq[b_safe][k];
            id0 = __dp4a(hv, w0[k], id0);
            id1 = __dp4a(hv, w1[k], id1);
        }
        float rs = s2prev * swh;
        float a0 = fmaf((float)id0, rs, xw.x);
        float a1 = fmaf((float)id1, rs, xw.y);

        // warp-level (max,min) via REDUX on order-preserving uints
        unsigned e0m = active ? fenc(a0) : 0u;
        unsigned e1m = active ? fenc(a1) : 0u;
        unsigned e0n = active ? fenc(a0) : 0xFFFFFFFFu;
        unsigned e1n = active ? fenc(a1) : 0xFFFFFFFFu;
        unsigned em = __reduce_max_sync(0xFFFFFFFFu, max(e0m, e1m));
        unsigned en = __reduce_min_sync(0xFFFFFFFFu, min(e0n, e1n));
        if (lane == 0) { partials[warp][0] = em; partials[warp][1] = en; }
        __syncthreads();   // barA

        if (warp == 0) {
            // CTA combine
            unsigned pm = (lane < NWARP) ? partials[lane][0] : 0u;
            unsigned pn = (lane < NWARP) ? partials[lane][1] : 0xFFFFFFFFu;
            pm = __reduce_max_sync(0xFFFFFFFFu, pm);
            pn = __reduce_min_sync(0xFFFFFFFFu, pn);
            if (lane == 0) {
                unsigned long long pk = (((unsigned long long)pm) << 32) | (unsigned long long)pn;
                unsigned long long a = slots_g + (unsigned long long)(t * NCTA + rank) * 8ull;
                asm volatile("st.relaxed.gpu.global.u64 [%0], %1;" :: "l"(a), "l"(pk) : "memory");
            }
            // poll all 8 CTAs' slots (sentinel: high word == 0)
            unsigned long long v = 0x00000000FFFFFFFFull;
            if (lane < NCTA) {
                unsigned long long a = slots_g + (unsigned long long)(t * NCTA + lane) * 8ull;
                unsigned hi;
                do {
                    asm volatile("ld.relaxed.gpu.global.u64 %0, [%1];" : "=l"(v) : "l"(a));
                    hi = (unsigned)(v >> 32);
                } while (hi == 0u);
            }
            unsigned gm = __reduce_max_sync(0xFFFFFFFFu, (unsigned)(v >> 32));
            unsigned gn = __reduce_min_sync(0xFFFFFFFFu, (unsigned)(v & 0xFFFFFFFFull));
            if (lane == 0) sh_comb = (((unsigned long long)gm) << 32) | (unsigned long long)gn;
        }
        __syncthreads();   // barC

        unsigned long long cv = sh_comb;
        float mx = fdec((unsigned)(cv >> 32));
        float mn = fdec((unsigned)(cv & 0xFFFFFFFFull));

        // gate-acc quant scale from global maxabs (bit-exact power-of-two)
        float inv1;
        float s1 = pot_scale(fmaxf(mx, -mn), &inv1);
        // output quant scale derived analytically: maxabs(tanh(q(acc))) = tanh(max(q(mx), -q(mn)))
        float qmx = qclip(rintf(mx * inv1)) * s1;
        float qmn = qclip(rintf(mn * inv1)) * s1;
        float habs = tanhf(fmaxf(qmx, -qmn));
        float inv2;
        float s2 = pot_scale(habs, &inv2);

        // elementwise: quant -> tanh -> quant (independent of the habs chain, overlaps)
        float q0 = qclip(rintf(a0 * inv1));
        float q1 = qclip(rintf(a1 * inv1));
        float t0 = tanhf(q0 * s1);
        float t1 = tanhf(q1 * s1);
        float n0 = qclip(rintf(t0 * inv2));
        float n1 = qclip(rintf(t1 * inv2));

        if (active) {
            *(float2*)(outp + (size_t)t * HH) = make_float2(n0 * s2, n1 * s2);
            unsigned short pk16 = (unsigned short)((((int)n0) & 0xFF) | ((((int)n1) & 0xFF) << 8));
            *((unsigned short*)((char*)&hq[b_safe][0] + h0i)) = pk16;
        }
        s2prev = s2;
        xw = xw_n;
        // hq rows are warp-private (batch never straddles a warp): warp fence suffices
        __syncwarp();
    }
}

// ---------------- launch ----------------
extern "C" void kernel_launch(void* const* d_in, const int* in_sizes, int n_in,
                              void* d_out, int out_size) {
    const float* x    = (const float*)d_in[0];
    const float* h0   = (const float*)d_in[1];
    const float* Wi   = (const float*)d_in[2];
    const float* Wh   = (const float*)d_in[3];
    const float* bias = (const float*)d_in[4];
    float* out = (float*)d_out;

    k_prep<<<1, 256>>>(Wi, Wh, bias, h0);
    k_absmax_x<<<1024, 256>>>(x, (BB * TT * DD) / 4);
    k_xw<<<(BB * TT) / 256, 256>>>(x, Wi, bias);
    k_scan<<<NCTA, SCAN_THREADS>>>(h0, out);
}